// round 5
// baseline (speedup 1.0000x reference)
#include <cuda_runtime.h>

// PerBandSoftAGC: out = x / (clip(EMA100(|x|), 1e-6)^alpha + 0.1)
// x: (32, 8, 16, 8192) fp32 -> 4096 rows of T=8192, channel kc = row % 128.
// EMA weights w_i = c*q^i (i<100), q = 1 - sigmoid(log_s), c = s/((1-q^100)+1e-8).
// Exact recurrence: M[t] = q*M[t-1] + c*|x[t]| - c*q^100*|x[t-100]|.

#define T_LEN   8192
#define KC_NUM  128
#define L_FIR   100
#define TPB     256
#define CPT     (T_LEN / TPB)        // 32 outputs per thread
#define VEC_IT  (T_LEN / (TPB * 4))  // 8 float4 iterations per thread

// 5-bit XOR swizzle: conflict-free for BOTH stride-32 scalar access
// (bank = const ^ perm(t)) and blocks-of-4 access (groups of 8 lanes get
// XOR constants differing in low 2 bits -> disjoint bank sets).
__device__ __forceinline__ int swz(int i) { return i ^ ((i >> 5) & 31); }

__global__ __launch_bounds__(TPB)
void per_band_soft_agc_kernel(const float* __restrict__ x,
                              const float* __restrict__ alpha_raw,
                              const float* __restrict__ log_s,
                              float* __restrict__ out)
{
    __shared__ float sx[T_LEN];   // 32 KB

    const int row = blockIdx.x;
    const int kc  = row & (KC_NUM - 1);
    const int tid = threadIdx.x;

    const float4* __restrict__ xr4 = (const float4*)(x   + (size_t)row * T_LEN);
    float4*       __restrict__ or4 = (float4*)      (out + (size_t)row * T_LEN);

    // ---- Stage row into smem: LDG.128 (coalesced) + 4 conflict-free scalar STS ----
    #pragma unroll
    for (int k = 0; k < VEC_IT; ++k) {
        const int   vi = tid + k * TPB;
        const float4 v = xr4[vi];
        const int    i = vi * 4;
        sx[swz(i + 0)] = v.x;
        sx[swz(i + 1)] = v.y;
        sx[swz(i + 2)] = v.z;
        sx[swz(i + 3)] = v.w;
    }

    // ---- Per-channel scalars (redundant per-thread; trivial) ----
    const float ls    = log_s[kc];
    const float s     = 1.0f / (1.0f + __expf(-ls));
    const float q     = 1.0f - s;
    const float qL    = __powf(q, (float)L_FIR);
    const float c     = s / ((1.0f - qL) + 1e-8f);
    const float cqL   = c * qL;
    const float ar    = alpha_raw[kc];
    const float alpha = 0.5f / (1.0f + __expf(-ar));

    __syncthreads();

    const int p0 = tid * CPT;

    // ---- FIR seed at p0 (exact; bounds recurrence error to 31 steps) ----
    // Lane t reads sx[swz(32t - i)]: constant low-5 bits -> conflict-free.
    float M = 0.0f;
    {
        const int taps = min(p0 + 1, L_FIR);
        float w = c;
        for (int i = 0; i < taps; ++i) {
            M = fmaf(w, fabsf(sx[swz(p0 - i)]), M);
            w *= q;
        }
    }

    float ov[CPT];
    {
        const float xp = sx[swz(p0)];
        const float g  = __powf(fmaxf(M, 1e-6f), alpha) + 0.1f;
        ov[0] = __fdividef(xp, g);
    }
    #pragma unroll
    for (int k = 1; k < CPT; ++k) {
        const int   p    = p0 + k;
        const float xp   = sx[swz(p)];
        const float xold = (p >= L_FIR) ? fabsf(sx[swz(p - L_FIR)]) : 0.0f;
        M = fmaf(q, M, fmaf(c, fabsf(xp), -cqL * xold));
        const float g = __powf(fmaxf(M, 1e-6f), alpha) + 0.1f;
        ov[k] = __fdividef(xp, g);
    }

    // ---- Transpose through smem so the global store is STG.128-coalesced ----
    __syncthreads();
    #pragma unroll
    for (int k = 0; k < CPT; ++k)          // stride-32 pattern: conflict-free
        sx[swz(p0 + k)] = ov[k];
    __syncthreads();
    #pragma unroll
    for (int k = 0; k < VEC_IT; ++k) {
        const int vi = tid + k * TPB;
        const int i  = vi * 4;
        float4 v;
        v.x = sx[swz(i + 0)];
        v.y = sx[swz(i + 1)];
        v.z = sx[swz(i + 2)];
        v.w = sx[swz(i + 3)];
        or4[vi] = v;
    }
}

extern "C" void kernel_launch(void* const* d_in, const int* in_sizes, int n_in,
                              void* d_out, int out_size)
{
    const float* x         = (const float*)d_in[0];
    const float* alpha_raw = (const float*)d_in[1];
    const float* log_s     = (const float*)d_in[2];
    float*       out       = (float*)d_out;

    const int rows = in_sizes[0] / T_LEN;   // 4096
    per_band_soft_agc_kernel<<<rows, TPB>>>(x, alpha_raw, log_s, out);
}

// round 8
// speedup vs baseline: 1.5837x; 1.5837x over previous
#include <cuda_runtime.h>

// PerBandSoftAGC: out = x / (clip(EMA100(|x|), 1e-6)^alpha + 0.1)
// x: (32, 8, 16, 8192) fp32 -> 4096 rows of T=8192, channel kc = row % 128.
// EMA weights w_i = c*q^i (i<100), q = 1 - sigmoid(log_s), c = s/((1-q^100)+1e-8).
// Linear recurrence M[t] = q*M[t-1] + u[t],  u[t] = c*|x[t]| - c*q^100*|x[t-100]| (lag term 0 for t<100).
//
// Structure: one WARP per 1024-element segment (8 segments/row). Per 32-element
// macro-step: coalesced LDG, weighted Kogge-Stone inclusive scan (5 shfl_up),
// one serial carry FMA, coalesced STG. Segment-start carry seeded by a
// warp-parallel 100-tap FIR (4 taps/lane + butterfly reduce). No smem, no bars.

#define T_LEN   8192
#define KC_NUM  128
#define L_FIR   100
#define SEG     1024
#define TPB     256
#define WARPS_PER_BLOCK (TPB / 32)

__global__ __launch_bounds__(TPB)
void per_band_soft_agc_kernel(const float* __restrict__ x,
                              const float* __restrict__ alpha_raw,
                              const float* __restrict__ log_s,
                              float* __restrict__ out)
{
    const unsigned FULL = 0xffffffffu;
    const int gw   = blockIdx.x * WARPS_PER_BLOCK + (threadIdx.x >> 5); // segment id
    const int lane = threadIdx.x & 31;
    const int row  = gw >> 3;                 // 8 segments per row
    const int o    = (gw & 7) * SEG;          // segment start within row
    const int kc   = row & (KC_NUM - 1);

    const float* __restrict__ xr   = x   + (size_t)row * T_LEN;
    float*       __restrict__ orow = out + (size_t)row * T_LEN;

    // ---- per-channel scalars (uniform across warp; broadcast LDG) ----
    const float ls    = log_s[kc];
    const float s     = 1.0f / (1.0f + __expf(-ls));
    const float q     = 1.0f - s;
    const float l2q   = __log2f(q);
    const float qL    = exp2f(l2q * (float)L_FIR);          // q^100
    const float c     = s / ((1.0f - qL) + 1e-8f);
    const float cqL   = c * qL;
    const float ar    = alpha_raw[kc];
    const float alpha = 0.5f / (1.0f + __expf(-ar));

    const float qlane = exp2f(l2q * (float)lane);           // q^lane
    const float qp1   = q * qlane;                          // q^(lane+1)
    const float q32   = exp2f(l2q * 32.0f);                 // q^32

    // ---- seed carry = M[o-1] via warp-parallel 100-tap FIR (o>0 => o>=1024) ----
    float carry = 0.0f;
    if (o > 0) {
        const float q64 = q32 * q32;
        const float q96 = q64 * q32;
        const int   b   = o - 1 - lane;                     // taps i = lane, lane+32, lane+64, lane+96
        float t = fabsf(xr[b]);
        t = fmaf(q32, fabsf(xr[b - 32]), t);
        t = fmaf(q64, fabsf(xr[b - 64]), t);
        if (lane < 4) t = fmaf(q96, fabsf(xr[b - 96]), t);
        t *= c * qlane;
        #pragma unroll
        for (int d = 16; d > 0; d >>= 1)
            t += __shfl_xor_sync(FULL, t, d);
        carry = t;                                          // exact M[o-1]
    }

    // ---- main loop: 32 macro-steps of 32 elements ----
    #pragma unroll 4
    for (int step = 0; step < SEG / 32; ++step) {
        const int p  = o + step * 32 + lane;
        const float xv = xr[p];                             // coalesced
        const float xo = (p >= L_FIR) ? xr[p - L_FIR] : 0.0f; // L1-resident re-read
        float v = fmaf(c, fabsf(xv), -cqL * fabsf(xo));     // u[p]

        // weighted inclusive scan: v_l = sum_{j<=l} q^(l-j) u_j
        float m = q;
        #pragma unroll
        for (int d = 1; d < 32; d <<= 1) {
            const float t = __shfl_up_sync(FULL, v, d);
            if (lane >= d) v = fmaf(m, t, v);
            m = m * m;                                      // q, q^2, q^4, q^8, q^16
        }
        const float v31 = __shfl_sync(FULL, v, 31);
        const float M   = fmaf(qp1, carry, v);              // full M[p]
        carry = fmaf(q32, carry, v31);                      // only serial dep across steps

        const float Mc = fmaxf(M, 1e-6f);
        const float g  = __powf(Mc, alpha) + 0.1f;          // MUFU lg2+ex2
        orow[p] = __fdividef(xv, g);                        // coalesced
    }
}

extern "C" void kernel_launch(void* const* d_in, const int* in_sizes, int n_in,
                              void* d_out, int out_size)
{
    const float* x         = (const float*)d_in[0];
    const float* alpha_raw = (const float*)d_in[1];
    const float* log_s     = (const float*)d_in[2];
    float*       out       = (float*)d_out;

    const int rows   = in_sizes[0] / T_LEN;                 // 4096
    const int warps  = rows * (T_LEN / SEG);                // 32768 segments
    const int blocks = warps / WARPS_PER_BLOCK;             // 4096
    per_band_soft_agc_kernel<<<blocks, TPB>>>(x, alpha_raw, log_s, out);
}

// round 9
// speedup vs baseline: 2.3878x; 1.5077x over previous
#include <cuda_runtime.h>

// PerBandSoftAGC: out = x / (clip(EMA100(|x|), 1e-6)^alpha + 0.1)
// x: (32, 8, 16, 8192) fp32 -> 4096 rows of T=8192, channel kc = row % 128.
// EMA weights w_i = c*q^i (i<100), q = 1 - sigmoid(log_s), c = s/((1-q^100)+1e-8).
// Linear recurrence M[t] = q*M[t-1] + u[t], u[t] = c|x[t]| - c*q^100*|x[t-100]|.
//
// One WARP per 1024-elem segment. Macro-step = 128 elems: each lane owns a
// float4 (4 consecutive). Local serial scan (3 FMA) -> warp Kogge-Stone on the
// lane aggregate with ratio q^4 (5 SHFL) -> recombine. Carry seeded by a
// warp-parallel 100-tap FIR. No smem, no block barriers.

#define T_LEN   8192
#define KC_NUM  128
#define L_FIR   100
#define SEG     1024
#define TPB     256
#define WARPS_PER_BLOCK (TPB / 32)
#define VPT     4
#define MACRO   (32 * VPT)        // 128 elems per warp macro-step
#define STEPS   (SEG / MACRO)     // 8

__global__ __launch_bounds__(TPB)
void per_band_soft_agc_kernel(const float* __restrict__ x,
                              const float* __restrict__ alpha_raw,
                              const float* __restrict__ log_s,
                              float* __restrict__ out)
{
    const unsigned FULL = 0xffffffffu;
    const int gw   = blockIdx.x * WARPS_PER_BLOCK + (threadIdx.x >> 5);
    const int lane = threadIdx.x & 31;
    const int row  = gw >> 3;                 // 8 segments per row
    const int o    = (gw & 7) * SEG;
    const int kc   = row & (KC_NUM - 1);

    const float* __restrict__ xr   = x   + (size_t)row * T_LEN;
    float*       __restrict__ orow = out + (size_t)row * T_LEN;

    // ---- per-channel scalars (warp-uniform) ----
    const float ls    = log_s[kc];
    const float s     = 1.0f / (1.0f + __expf(-ls));
    const float q     = 1.0f - s;
    const float l2q   = __log2f(q);
    const float qL    = exp2f(l2q * (float)L_FIR);          // q^100
    const float c     = s / ((1.0f - qL) + 1e-8f);
    const float ncqL  = -c * qL;
    const float ar    = alpha_raw[kc];
    const float alpha = 0.5f / (1.0f + __expf(-ar));

    // hoisted powers of q (loop-invariant)
    const float q1 = q, q2 = q * q, q3 = q2 * q, q4 = q2 * q2;
    const float r1 = q4, r2 = r1 * r1, r4 = r2 * r2, r8 = r4 * r4, r16 = r8 * r8;
    const float q128 = r16 * r16;                            // q^128
    const float q4l  = exp2f(l2q * (float)(4 * lane));       // q^(4*lane)
    const float q32  = exp2f(l2q * 32.0f);
    const float qlane = exp2f(l2q * (float)lane);

    // ---- seed carry = M[o-1] via warp-parallel 100-tap FIR ----
    float carry = 0.0f;
    if (o > 0) {
        const float q64 = q32 * q32;
        const float q96 = q64 * q32;
        const int   b   = o - 1 - lane;
        float t = fabsf(xr[b]);
        t = fmaf(q32, fabsf(xr[b - 32]), t);
        t = fmaf(q64, fabsf(xr[b - 64]), t);
        if (lane < 4) t = fmaf(q96, fabsf(xr[b - 96]), t);
        t *= c * qlane;
        #pragma unroll
        for (int d = 16; d > 0; d >>= 1)
            t += __shfl_xor_sync(FULL, t, d);
        carry = t;                                           // exact M[o-1]
    }

    // ---- main loop: 8 macro-steps of 128 elements ----
    #pragma unroll 2
    for (int step = 0; step < STEPS; ++step) {
        const int pb = o + step * MACRO + lane * VPT;        // vector base (16B aligned)
        const float4 xv = *(const float4*)(xr + pb);         // LDG.128, coalesced
        float4 xo;
        if (pb >= L_FIR) xo = *(const float4*)(xr + pb - L_FIR); // aligned (100 % 4 == 0)
        else             xo = make_float4(0.f, 0.f, 0.f, 0.f);

        // u_j = c|x| + (-c q^100)|x_lag|
        const float u0 = fmaf(c, fabsf(xv.x), ncqL * fabsf(xo.x));
        const float u1 = fmaf(c, fabsf(xv.y), ncqL * fabsf(xo.y));
        const float u2 = fmaf(c, fabsf(xv.z), ncqL * fabsf(xo.z));
        const float u3 = fmaf(c, fabsf(xv.w), ncqL * fabsf(xo.w));

        // local inclusive weighted scan over the 4 owned elems
        const float a0 = u0;
        const float a1 = fmaf(q1, a0, u1);
        const float a2 = fmaf(q1, a1, u2);
        const float a3 = fmaf(q1, a2, u3);

        // warp inclusive scan of lane aggregates with ratio q^4
        float S = a3;
        { float t = __shfl_up_sync(FULL, S, 1);  if (lane >= 1)  S = fmaf(r1,  t, S); }
        { float t = __shfl_up_sync(FULL, S, 2);  if (lane >= 2)  S = fmaf(r2,  t, S); }
        { float t = __shfl_up_sync(FULL, S, 4);  if (lane >= 4)  S = fmaf(r4,  t, S); }
        { float t = __shfl_up_sync(FULL, S, 8);  if (lane >= 8)  S = fmaf(r8,  t, S); }
        { float t = __shfl_up_sync(FULL, S, 16); if (lane >= 16) S = fmaf(r16, t, S); }

        // exclusive prefix from lanes below + incoming carry
        const float Ex = __shfl_up_sync(FULL, S, 1);
        const float E  = (lane >= 1) ? Ex : 0.0f;
        const float w  = fmaf(q4l, carry, E);

        const float S31 = __shfl_sync(FULL, S, 31);
        carry = fmaf(q128, carry, S31);                      // only serial cross-step dep

        // full M for the 4 owned elems, then gain + divide
        const float M0 = fmaf(q1, w, a0);
        const float M1 = fmaf(q2, w, a1);
        const float M2 = fmaf(q3, w, a2);
        const float M3 = fmaf(q4, w, a3);

        float4 r;
        r.x = __fdividef(xv.x, __powf(fmaxf(M0, 1e-6f), alpha) + 0.1f);
        r.y = __fdividef(xv.y, __powf(fmaxf(M1, 1e-6f), alpha) + 0.1f);
        r.z = __fdividef(xv.z, __powf(fmaxf(M2, 1e-6f), alpha) + 0.1f);
        r.w = __fdividef(xv.w, __powf(fmaxf(M3, 1e-6f), alpha) + 0.1f);
        *(float4*)(orow + pb) = r;                           // STG.128, coalesced
    }
}

extern "C" void kernel_launch(void* const* d_in, const int* in_sizes, int n_in,
                              void* d_out, int out_size)
{
    const float* x         = (const float*)d_in[0];
    const float* alpha_raw = (const float*)d_in[1];
    const float* log_s     = (const float*)d_in[2];
    float*       out       = (float*)d_out;

    const int rows   = in_sizes[0] / T_LEN;                 // 4096
    const int warps  = rows * (T_LEN / SEG);                // 32768
    const int blocks = warps / WARPS_PER_BLOCK;             // 4096
    per_band_soft_agc_kernel<<<blocks, TPB>>>(x, alpha_raw, log_s, out);
}

// round 10
// speedup vs baseline: 2.5771x; 1.0793x over previous
#include <cuda_runtime.h>

// PerBandSoftAGC: out = x / (clip(EMA100(|x|), 1e-6)^alpha + 0.1)
// x: (32, 8, 16, 8192) fp32 -> 4096 rows of T=8192, channel kc = row % 128.
// EMA weights w_i = c*q^i (i<100), q = 1 - sigmoid(log_s), c = s/((1-q^100)+1e-8).
// Linear recurrence M[t] = q*M[t-1] + u[t], u[t] = c|x[t]| - c*q^100*|x[t-100]|.
//
// One WARP per 1024-elem segment. Macro-step = 256 elems: each lane owns 8
// consecutive floats (2x float4). Local serial scan (7 FMA) -> warp Kogge-Stone
// on the lane aggregate with ratio q^8 (5 shfl) -> recombine. Carry seeded by a
// warp-parallel 100-tap FIR. No smem, no block barriers.

#define T_LEN   8192
#define KC_NUM  128
#define L_FIR   100
#define SEG     1024
#define TPB     256
#define WARPS_PER_BLOCK (TPB / 32)
#define VPT     8
#define MACRO   (32 * VPT)        // 256 elems per warp macro-step
#define STEPS   (SEG / MACRO)     // 4

__global__ __launch_bounds__(TPB)
void per_band_soft_agc_kernel(const float* __restrict__ x,
                              const float* __restrict__ alpha_raw,
                              const float* __restrict__ log_s,
                              float* __restrict__ out)
{
    const unsigned FULL = 0xffffffffu;
    const int gw   = blockIdx.x * WARPS_PER_BLOCK + (threadIdx.x >> 5);
    const int lane = threadIdx.x & 31;
    const int row  = gw >> 3;                 // 8 segments per row
    const int o    = (gw & 7) * SEG;
    const int kc   = row & (KC_NUM - 1);

    const float* __restrict__ xr   = x   + (size_t)row * T_LEN;
    float*       __restrict__ orow = out + (size_t)row * T_LEN;

    // ---- per-channel scalars (warp-uniform) ----
    const float ls    = log_s[kc];
    const float s     = 1.0f / (1.0f + __expf(-ls));
    const float q     = 1.0f - s;
    const float l2q   = __log2f(q);
    const float qL    = exp2f(l2q * (float)L_FIR);          // q^100
    const float c     = s / ((1.0f - qL) + 1e-8f);
    const float ncqL  = -c * qL;
    const float ar    = alpha_raw[kc];
    const float alpha = 0.5f / (1.0f + __expf(-ar));

    // hoisted powers of q (all loop-invariant)
    float qp[VPT];                                           // q^1 .. q^8
    qp[0] = q;
    #pragma unroll
    for (int j = 1; j < VPT; ++j) qp[j] = qp[j - 1] * q;
    const float r1 = qp[VPT - 1];                            // q^8
    const float r2 = r1 * r1, r4 = r2 * r2, r8 = r4 * r4, r16 = r8 * r8;
    const float q256 = r16 * r16;                            // q^256
    const float q8l  = exp2f(l2q * (float)(VPT * lane));     // q^(8*lane)
    const float q32  = exp2f(l2q * 32.0f);
    const float qlane = exp2f(l2q * (float)lane);

    // ---- seed carry = M[o-1] via warp-parallel 100-tap FIR ----
    float carry = 0.0f;
    if (o > 0) {
        const float q64 = q32 * q32;
        const float q96 = q64 * q32;
        const int   b   = o - 1 - lane;
        float t = fabsf(xr[b]);
        t = fmaf(q32, fabsf(xr[b - 32]), t);
        t = fmaf(q64, fabsf(xr[b - 64]), t);
        if (lane < 4) t = fmaf(q96, fabsf(xr[b - 96]), t);
        t *= c * qlane;
        #pragma unroll
        for (int d = 16; d > 0; d >>= 1)
            t += __shfl_xor_sync(FULL, t, d);
        carry = t;                                           // exact M[o-1]
    }

    // ---- main loop: 4 macro-steps of 256 elements ----
    #pragma unroll 2
    for (int step = 0; step < STEPS; ++step) {
        const int pb = o + step * MACRO + lane * VPT;        // 8-aligned -> 16B aligned

        float xv[VPT];
        {   // two LDG.128, coalesced
            const float4 v0 = *(const float4*)(xr + pb);
            const float4 v1 = *(const float4*)(xr + pb + 4);
            xv[0] = v0.x; xv[1] = v0.y; xv[2] = v0.z; xv[3] = v0.w;
            xv[4] = v1.x; xv[5] = v1.y; xv[6] = v1.z; xv[7] = v1.w;
        }

        float xo[VPT];
        if (pb >= L_FIR) {                                   // (pb-100) % 4 == 0 -> aligned
            const float4 v0 = *(const float4*)(xr + pb - L_FIR);
            const float4 v1 = *(const float4*)(xr + pb - L_FIR + 4);
            xo[0] = v0.x; xo[1] = v0.y; xo[2] = v0.z; xo[3] = v0.w;
            xo[4] = v1.x; xo[5] = v1.y; xo[6] = v1.z; xo[7] = v1.w;
        } else {                                             // first segment, step 0 only
            #pragma unroll
            for (int j = 0; j < VPT; ++j) {
                const int p = pb + j;
                xo[j] = (p >= L_FIR) ? xr[p - L_FIR] : 0.0f;
            }
        }

        // u_j then local inclusive weighted scan (in place)
        float a[VPT];
        a[0] = fmaf(c, fabsf(xv[0]), ncqL * fabsf(xo[0]));
        #pragma unroll
        for (int j = 1; j < VPT; ++j) {
            const float u = fmaf(c, fabsf(xv[j]), ncqL * fabsf(xo[j]));
            a[j] = fmaf(q, a[j - 1], u);
        }

        // warp inclusive scan of lane aggregates with ratio q^8
        float S = a[VPT - 1];
        { float t = __shfl_up_sync(FULL, S, 1);  if (lane >= 1)  S = fmaf(r1,  t, S); }
        { float t = __shfl_up_sync(FULL, S, 2);  if (lane >= 2)  S = fmaf(r2,  t, S); }
        { float t = __shfl_up_sync(FULL, S, 4);  if (lane >= 4)  S = fmaf(r4,  t, S); }
        { float t = __shfl_up_sync(FULL, S, 8);  if (lane >= 8)  S = fmaf(r8,  t, S); }
        { float t = __shfl_up_sync(FULL, S, 16); if (lane >= 16) S = fmaf(r16, t, S); }

        // exclusive prefix from lanes below + incoming carry
        const float Ex = __shfl_up_sync(FULL, S, 1);
        const float E  = (lane >= 1) ? Ex : 0.0f;
        const float w  = fmaf(q8l, carry, E);

        const float S31 = __shfl_sync(FULL, S, 31);
        carry = fmaf(q256, carry, S31);                      // only serial cross-step dep

        // full M, gain, divide, store
        float4 r0, r1v;
        float* rp = &r0.x;
        #pragma unroll
        for (int j = 0; j < VPT; ++j) {
            const float M  = fmaf(qp[j], w, a[j]);
            const float g  = __powf(fmaxf(M, 1e-6f), alpha) + 0.1f;
            const float rj = __fdividef(xv[j], g);
            if (j < 4) (&r0.x)[j] = rj; else (&r1v.x)[j - 4] = rj;
        }
        (void)rp;
        *(float4*)(orow + pb)     = r0;                      // STG.128, coalesced
        *(float4*)(orow + pb + 4) = r1v;
    }
}

extern "C" void kernel_launch(void* const* d_in, const int* in_sizes, int n_in,
                              void* d_out, int out_size)
{
    const float* x         = (const float*)d_in[0];
    const float* alpha_raw = (const float*)d_in[1];
    const float* log_s     = (const float*)d_in[2];
    float*       out       = (float*)d_out;

    const int rows   = in_sizes[0] / T_LEN;                 // 4096
    const int warps  = rows * (T_LEN / SEG);                // 32768
    const int blocks = warps / WARPS_PER_BLOCK;             // 4096
    per_band_soft_agc_kernel<<<blocks, TPB>>>(x, alpha_raw, log_s, out);
}